// round 5
// baseline (speedup 1.0000x reference)
#include <cuda_runtime.h>

// LieTransport: out[b,c,y,x,r] = bilinear_border_sample(h_prev[b,c,:,:,r], grid(b,y,x))
// Shapes: h_prev [4,16,128,128,64] f32, flow [4,2,128,128] f32, dt [4] f32.
// Latency-limited gather. Coordinates/weights/indices are identical across all
// C=16 channels: compute once per thread, then software-pipeline the 16 channel
// gathers (next iteration's 4 loads issued before current blend) so the
// flow->coord dependency is paid once per 16 gather rounds and each thread
// keeps ~8 loads in flight. 16 lanes per pixel keeps every load a full-line op.

#define B 4
#define C 16
#define H 128
#define W 128
#define R 64
#define R4 (R / 4)            // 16 float4 per pixel
#define HW (H * W)
#define CSTRIDE (HW * R4)     // float4 stride between channels (262144)

__device__ __forceinline__ float4 f4_lerp(float4 a, float4 b, float t) {
    float4 r;
    r.x = fmaf(t, b.x - a.x, a.x);
    r.y = fmaf(t, b.y - a.y, a.y);
    r.z = fmaf(t, b.z - a.z, a.z);
    r.w = fmaf(t, b.w - a.w, a.w);
    return r;
}

__global__ void __launch_bounds__(256, 6)
lie_transport_kernel(const float4* __restrict__ h4,
                     const float* __restrict__ flow,
                     const float* __restrict__ dt,
                     float4* __restrict__ out4)
{
    // idx bits (fastest -> slowest): r4 (16), x (128), y (128), b (4); c looped
    int idx = blockIdx.x * blockDim.x + threadIdx.x;   // 0 .. 2^20-1
    int r4 = idx & (R4 - 1);
    int x  = (idx >> 4) & (W - 1);
    int y  = (idx >> 11) & (H - 1);
    int b  = idx >> 18;

    // ---- per-pixel sampling coordinates (once per 16 channels) ----
    float d   = __ldg(&dt[b]);
    float fdx = __ldg(&flow[((b * 2 + 0) * H + y) * W + x]);
    float fdy = __ldg(&flow[((b * 2 + 1) * H + y) * W + x]);

    float gx = fmaf((float)x, 2.0f / (W - 1), -1.0f) - fdx * d;
    float gy = fmaf((float)y, 2.0f / (H - 1), -1.0f) - fdy * d;

    float xs = fminf(fmaxf(((gx + 1.0f) * (float)W - 1.0f) * 0.5f, 0.0f), (float)(W - 1));
    float ys = fminf(fmaxf(((gy + 1.0f) * (float)H - 1.0f) * 0.5f, 0.0f), (float)(H - 1));

    float x0f = floorf(xs);
    float y0f = floorf(ys);
    float wx = xs - x0f;
    float wy = ys - y0f;

    int x0 = (int)x0f;
    int y0 = (int)y0f;
    int x1 = min(x0 + 1, W - 1);
    int y1 = min(y0 + 1, H - 1);

    // channel-0 float4 indices (int32: total float4 count = 2^26, fits)
    int bbase = b * (C * CSTRIDE);
    int i00 = bbase + (y0 * W + x0) * R4 + r4;
    int i01 = bbase + (y0 * W + x1) * R4 + r4;
    int i10 = bbase + (y1 * W + x0) * R4 + r4;
    int i11 = bbase + (y1 * W + x1) * R4 + r4;
    int io  = bbase + (y  * W + x ) * R4 + r4;

    // ---- software-pipelined channel loop ----
    float4 v00 = __ldg(h4 + i00);
    float4 v01 = __ldg(h4 + i01);
    float4 v10 = __ldg(h4 + i10);
    float4 v11 = __ldg(h4 + i11);

#pragma unroll 4
    for (int c = 0; c < C; ++c) {
        float4 n00, n01, n10, n11;
        if (c + 1 < C) {
            i00 += CSTRIDE; i01 += CSTRIDE; i10 += CSTRIDE; i11 += CSTRIDE;
            n00 = __ldg(h4 + i00);
            n01 = __ldg(h4 + i01);
            n10 = __ldg(h4 + i10);
            n11 = __ldg(h4 + i11);
        }
        float4 top = f4_lerp(v00, v01, wx);
        float4 bot = f4_lerp(v10, v11, wx);
        out4[io] = f4_lerp(top, bot, wy);
        io += CSTRIDE;
        v00 = n00; v01 = n01; v10 = n10; v11 = n11;
    }
}

extern "C" void kernel_launch(void* const* d_in, const int* in_sizes, int n_in,
                              void* d_out, int out_size)
{
    const float* h_prev = nullptr;
    const float* flow   = nullptr;
    const float* dt     = nullptr;
    for (int i = 0; i < n_in; ++i) {
        if (in_sizes[i] == B * C * H * W * R)      h_prev = (const float*)d_in[i];
        else if (in_sizes[i] == B * 2 * H * W)     flow   = (const float*)d_in[i];
        else if (in_sizes[i] == B)                 dt     = (const float*)d_in[i];
    }

    int total = B * H * W * R4;                    // 1,048,576 threads
    int threads = 256;
    int blocks = total / threads;                  // 4,096

    lie_transport_kernel<<<blocks, threads>>>(
        (const float4*)h_prev, flow, dt, (float4*)d_out);
}

// round 6
// speedup vs baseline: 1.3377x; 1.3377x over previous
#include <cuda_runtime.h>

// LieTransport, two-phase:
//  1) precompute per-(b,y,x) bilinear records: 4 corner offsets + (wx,wy)  [65536 recs]
//  2) main gather kernel in the proven R1 layout (1 float4/thread, 16 lanes/pixel)
//     loads the record (broadcast), 4 gathers, 12-FMA blend, store.
// Removes flow load + ~30 coord instrs from the main kernel's dependent chain.

#define B 4
#define C 16
#define H 128
#define W 128
#define R 64
#define R4 (R / 4)            // 16 float4 per pixel
#define HW (H * W)
#define NPIX (B * HW)         // 65536 records

__device__ int4   g_cidx[NPIX];   // corner float4-offsets within one (b,c) image
__device__ float2 g_wxy[NPIX];    // (wx, wy)

__global__ void __launch_bounds__(256)
precompute_kernel(const float* __restrict__ flow,
                  const float* __restrict__ dt)
{
    int t = blockIdx.x * blockDim.x + threadIdx.x;   // 0 .. NPIX-1
    int x = t & (W - 1);
    int y = (t >> 7) & (H - 1);
    int b = t >> 14;

    float d   = __ldg(&dt[b]);
    float fdx = __ldg(&flow[((b * 2 + 0) * H + y) * W + x]);
    float fdy = __ldg(&flow[((b * 2 + 1) * H + y) * W + x]);

    float gx = fmaf((float)x, 2.0f / (W - 1), -1.0f) - fdx * d;
    float gy = fmaf((float)y, 2.0f / (H - 1), -1.0f) - fdy * d;

    float xs = fminf(fmaxf(((gx + 1.0f) * (float)W - 1.0f) * 0.5f, 0.0f), (float)(W - 1));
    float ys = fminf(fmaxf(((gy + 1.0f) * (float)H - 1.0f) * 0.5f, 0.0f), (float)(H - 1));

    float x0f = floorf(xs);
    float y0f = floorf(ys);

    int x0 = (int)x0f;
    int y0 = (int)y0f;
    int x1 = min(x0 + 1, W - 1);
    int y1 = min(y0 + 1, H - 1);

    int4 ci;
    ci.x = (y0 * W + x0) * R4;
    ci.y = (y0 * W + x1) * R4;
    ci.z = (y1 * W + x0) * R4;
    ci.w = (y1 * W + x1) * R4;
    g_cidx[t] = ci;
    g_wxy[t]  = make_float2(xs - x0f, ys - y0f);
}

__device__ __forceinline__ float4 f4_lerp(float4 a, float4 b, float t) {
    float4 r;
    r.x = fmaf(t, b.x - a.x, a.x);
    r.y = fmaf(t, b.y - a.y, a.y);
    r.z = fmaf(t, b.z - a.z, a.z);
    r.w = fmaf(t, b.w - a.w, a.w);
    return r;
}

__global__ void __launch_bounds__(256)
lie_transport_kernel(const float4* __restrict__ h4,
                     float4* __restrict__ out4)
{
    // idx bits (fastest -> slowest): r4 (4b), x (7b), y (7b), c (4b), b (2b)
    int idx = blockIdx.x * blockDim.x + threadIdx.x;   // 0 .. 2^24-1
    int r4  = idx & (R4 - 1);

    // record index = (b<<14) | (y<<7) | x
    int p = ((idx >> 22) << 14) | ((idx >> 4) & 0x3FFF);

    int4   ci = __ldg(&g_cidx[p]);
    float2 w  = __ldg(&g_wxy[p]);

    // (b*C + c) image base in float4 units, plus r4 lane offset
    int base = (idx >> 18) * (HW * R4) + r4;

    float4 v00 = __ldg(h4 + base + ci.x);
    float4 v01 = __ldg(h4 + base + ci.y);
    float4 v10 = __ldg(h4 + base + ci.z);
    float4 v11 = __ldg(h4 + base + ci.w);

    float4 top = f4_lerp(v00, v01, w.x);
    float4 bot = f4_lerp(v10, v11, w.x);
    out4[idx]  = f4_lerp(top, bot, w.y);
}

extern "C" void kernel_launch(void* const* d_in, const int* in_sizes, int n_in,
                              void* d_out, int out_size)
{
    const float* h_prev = nullptr;
    const float* flow   = nullptr;
    const float* dt     = nullptr;
    for (int i = 0; i < n_in; ++i) {
        if (in_sizes[i] == B * C * H * W * R)      h_prev = (const float*)d_in[i];
        else if (in_sizes[i] == B * 2 * H * W)     flow   = (const float*)d_in[i];
        else if (in_sizes[i] == B)                 dt     = (const float*)d_in[i];
    }

    precompute_kernel<<<NPIX / 256, 256>>>(flow, dt);

    int total = B * C * H * W * R4;                // 16,777,216 threads
    lie_transport_kernel<<<total / 256, 256>>>(
        (const float4*)h_prev, (float4*)d_out);
}

// round 7
// speedup vs baseline: 1.3381x; 1.0003x over previous
#include <cuda_runtime.h>

// LieTransport: out[b,c,y,x,r] = bilinear_border_sample(h_prev[b,c,:,:,r], grid(b,y,x))
// Shapes: h_prev [4,16,128,128,64] f32, flow [4,2,128,128] f32, dt [4] f32.
// Fused single kernel: each 256-thread block = 16 pixels x 16 r4 lanes.
// Lanes 0-15 of warp 0 compute the 16 per-pixel bilinear records (corner offsets
// + weights) into smem; after one barrier all threads read their record via
// broadcast LDS and do 4 full-line gathers + 12-FMA blend + coalesced store.
// This keeps the short gather chain of the two-phase version without the
// second-launch overhead.

#define B 4
#define C 16
#define H 128
#define W 128
#define R 64
#define R4 (R / 4)            // 16 float4 per pixel
#define HW (H * W)

__device__ __forceinline__ float4 f4_lerp(float4 a, float4 b, float t) {
    float4 r;
    r.x = fmaf(t, b.x - a.x, a.x);
    r.y = fmaf(t, b.y - a.y, a.y);
    r.z = fmaf(t, b.z - a.z, a.z);
    r.w = fmaf(t, b.w - a.w, a.w);
    return r;
}

__global__ void __launch_bounds__(256)
lie_transport_kernel(const float4* __restrict__ h4,
                     const float* __restrict__ flow,
                     const float* __restrict__ dt,
                     float4* __restrict__ out4)
{
    // global idx bits (fastest -> slowest): r4 (4), x (7), y (7), c (4), b (2)
    // one block = 16 consecutive pixels (same b,y,c; x0..x0+15), 16 lanes each
    __shared__ int4   s_ci[16];   // corner float4-offsets within one (b,c) image
    __shared__ float2 s_w[16];    // (wx, wy)

    int idx0 = blockIdx.x << 8;               // first idx of block
    int tid  = threadIdx.x;

    if (tid < 16) {
        int x = (((idx0 >> 4) & (W - 1)) | tid);   // x0 is 16-aligned
        int y = (idx0 >> 11) & (H - 1);
        int b = idx0 >> 22;

        float d   = __ldg(&dt[b]);
        float fdx = __ldg(&flow[((b * 2 + 0) * H + y) * W + x]);
        float fdy = __ldg(&flow[((b * 2 + 1) * H + y) * W + x]);

        float gx = fmaf((float)x, 2.0f / (W - 1), -1.0f) - fdx * d;
        float gy = fmaf((float)y, 2.0f / (H - 1), -1.0f) - fdy * d;

        float xs = fminf(fmaxf(((gx + 1.0f) * (float)W - 1.0f) * 0.5f, 0.0f), (float)(W - 1));
        float ys = fminf(fmaxf(((gy + 1.0f) * (float)H - 1.0f) * 0.5f, 0.0f), (float)(H - 1));

        float x0f = floorf(xs);
        float y0f = floorf(ys);

        int cx0 = (int)x0f;
        int cy0 = (int)y0f;
        int cx1 = min(cx0 + 1, W - 1);
        int cy1 = min(cy0 + 1, H - 1);

        int4 ci;
        ci.x = (cy0 * W + cx0) * R4;
        ci.y = (cy0 * W + cx1) * R4;
        ci.z = (cy1 * W + cx0) * R4;
        ci.w = (cy1 * W + cx1) * R4;
        s_ci[tid] = ci;
        s_w[tid]  = make_float2(xs - x0f, ys - y0f);
    }
    __syncthreads();

    int pix = tid >> 4;            // which of the block's 16 pixels
    int r4  = tid & (R4 - 1);

    int4   ci = s_ci[pix];
    float2 w  = s_w[pix];

    // (b*C + c) image base in float4 units (uniform per block) + r4 lane
    int base = (blockIdx.x >> 10) * (HW * R4) + r4;

    float4 v00 = __ldg(h4 + base + ci.x);
    float4 v01 = __ldg(h4 + base + ci.y);
    float4 v10 = __ldg(h4 + base + ci.z);
    float4 v11 = __ldg(h4 + base + ci.w);

    float4 top = f4_lerp(v00, v01, w.x);
    float4 bot = f4_lerp(v10, v11, w.x);
    out4[idx0 + tid] = f4_lerp(top, bot, w.y);
}

extern "C" void kernel_launch(void* const* d_in, const int* in_sizes, int n_in,
                              void* d_out, int out_size)
{
    const float* h_prev = nullptr;
    const float* flow   = nullptr;
    const float* dt     = nullptr;
    for (int i = 0; i < n_in; ++i) {
        if (in_sizes[i] == B * C * H * W * R)      h_prev = (const float*)d_in[i];
        else if (in_sizes[i] == B * 2 * H * W)     flow   = (const float*)d_in[i];
        else if (in_sizes[i] == B)                 dt     = (const float*)d_in[i];
    }

    int total = B * C * H * W * R4;                // 16,777,216 threads
    lie_transport_kernel<<<total / 256, 256>>>(
        (const float4*)h_prev, flow, dt, (float4*)d_out);
}

// round 8
// speedup vs baseline: 1.3589x; 1.0155x over previous
#include <cuda_runtime.h>

// LieTransport, two-phase with PDL overlap:
//  1) precompute per-(b,y,x) bilinear records (corner offsets + weights), 65536 recs
//  2) main gather kernel (proven 93.7us config: 1 float4/thread, 16 lanes/pixel)
// Secondary is launched with programmatic stream serialization so its blocks
// dispatch while the primary drains; it calls cudaGridDependencySynchronize()
// after its record-independent preamble, hiding the ~4.6us two-launch gap.

#define B 4
#define C 16
#define H 128
#define W 128
#define R 64
#define R4 (R / 4)            // 16 float4 per pixel
#define HW (H * W)
#define NPIX (B * HW)         // 65536 records

__device__ int4   g_cidx[NPIX];   // corner float4-offsets within one (b,c) image
__device__ float2 g_wxy[NPIX];    // (wx, wy)

__global__ void __launch_bounds__(256)
precompute_kernel(const float* __restrict__ flow,
                  const float* __restrict__ dt)
{
    int t = blockIdx.x * blockDim.x + threadIdx.x;   // 0 .. NPIX-1
    int x = t & (W - 1);
    int y = (t >> 7) & (H - 1);
    int b = t >> 14;

    float d   = __ldg(&dt[b]);
    float fdx = __ldg(&flow[((b * 2 + 0) * H + y) * W + x]);
    float fdy = __ldg(&flow[((b * 2 + 1) * H + y) * W + x]);

    float gx = fmaf((float)x, 2.0f / (W - 1), -1.0f) - fdx * d;
    float gy = fmaf((float)y, 2.0f / (H - 1), -1.0f) - fdy * d;

    float xs = fminf(fmaxf(((gx + 1.0f) * (float)W - 1.0f) * 0.5f, 0.0f), (float)(W - 1));
    float ys = fminf(fmaxf(((gy + 1.0f) * (float)H - 1.0f) * 0.5f, 0.0f), (float)(H - 1));

    float x0f = floorf(xs);
    float y0f = floorf(ys);

    int x0 = (int)x0f;
    int y0 = (int)y0f;
    int x1 = min(x0 + 1, W - 1);
    int y1 = min(y0 + 1, H - 1);

    int4 ci;
    ci.x = (y0 * W + x0) * R4;
    ci.y = (y0 * W + x1) * R4;
    ci.z = (y1 * W + x0) * R4;
    ci.w = (y1 * W + x1) * R4;
    g_cidx[t] = ci;
    g_wxy[t]  = make_float2(xs - x0f, ys - y0f);

#if __CUDA_ARCH__ >= 900
    cudaTriggerProgrammaticLaunchCompletion();
#endif
}

__device__ __forceinline__ float4 f4_lerp(float4 a, float4 b, float t) {
    float4 r;
    r.x = fmaf(t, b.x - a.x, a.x);
    r.y = fmaf(t, b.y - a.y, a.y);
    r.z = fmaf(t, b.z - a.z, a.z);
    r.w = fmaf(t, b.w - a.w, a.w);
    return r;
}

__global__ void __launch_bounds__(256)
lie_transport_kernel(const float4* __restrict__ h4,
                     float4* __restrict__ out4)
{
    // idx bits (fastest -> slowest): r4 (4b), x (7b), y (7b), c (4b), b (2b)
    int idx = blockIdx.x * blockDim.x + threadIdx.x;   // 0 .. 2^24-1
    int r4  = idx & (R4 - 1);

    // record index = (b<<14) | (y<<7) | x   -- independent of records
    int p    = ((idx >> 22) << 14) | ((idx >> 4) & 0x3FFF);
    int base = (idx >> 18) * (HW * R4) + r4;           // (b*C + c) image base

#if __CUDA_ARCH__ >= 900
    cudaGridDependencySynchronize();                   // wait for precompute results
#endif

    int4   ci = __ldg(&g_cidx[p]);
    float2 w  = __ldg(&g_wxy[p]);

    float4 v00 = __ldg(h4 + base + ci.x);
    float4 v01 = __ldg(h4 + base + ci.y);
    float4 v10 = __ldg(h4 + base + ci.z);
    float4 v11 = __ldg(h4 + base + ci.w);

    float4 top = f4_lerp(v00, v01, w.x);
    float4 bot = f4_lerp(v10, v11, w.x);
    out4[idx]  = f4_lerp(top, bot, w.y);
}

extern "C" void kernel_launch(void* const* d_in, const int* in_sizes, int n_in,
                              void* d_out, int out_size)
{
    const float* h_prev = nullptr;
    const float* flow   = nullptr;
    const float* dt     = nullptr;
    for (int i = 0; i < n_in; ++i) {
        if (in_sizes[i] == B * C * H * W * R)      h_prev = (const float*)d_in[i];
        else if (in_sizes[i] == B * 2 * H * W)     flow   = (const float*)d_in[i];
        else if (in_sizes[i] == B)                 dt     = (const float*)d_in[i];
    }

    // Primary: compute records
    precompute_kernel<<<NPIX / 256, 256>>>(flow, dt);

    // Secondary: PDL launch so it overlaps the primary's tail
    int total = B * C * H * W * R4;                // 16,777,216 threads
    cudaLaunchConfig_t cfg = {};
    cfg.gridDim  = dim3(total / 256);
    cfg.blockDim = dim3(256);
    cfg.dynamicSmemBytes = 0;
    cfg.stream = 0;
    cudaLaunchAttribute attrs[1];
    attrs[0].id = cudaLaunchAttributeProgrammaticStreamSerialization;
    attrs[0].val.programmaticStreamSerializationAllowed = 1;
    cfg.attrs = attrs;
    cfg.numAttrs = 1;
    cudaLaunchKernelEx(&cfg, lie_transport_kernel,
                       (const float4*)h_prev, (float4*)d_out);
}